// round 12
// baseline (speedup 1.0000x reference)
#include <cuda_runtime.h>
#include <cuda_fp16.h>
#include <cstdint>

// Problem constants
#define KVC   512
#define NH    16
#define HD    64
#define HWSZ  4096
#define NB    32
#define MTOT  (NB*HWSZ)     // 131072 pixels
#define NVAL  1024          // NH*HD value columns

// value-kernel tiles: BM=128 x BN=64, 256 threads (8 warps, 4x2), warp tile 32x32
#define BM      128
#define BN      64
#define BK      32
#define NCHUNK  (KVC/BK)    // 16
#define NSTAGE  4
#define ROWB    80          // 32 fp16 = 64B + 16B pad (conflict-free ldmatrix)
#define A_BYTES (BM*ROWB)              // 10240
#define STAGE_B ((BM+BN)*ROWB)         // 15360
#define OFF_RED (NSTAGE*STAGE_B)       // red[8][32] floats = 1024 B
#define OFF_BV  (OFF_RED + 1024)       // bv tile [64] = 256 B
#define SMEMB   (OFF_BV + BN*4)        // 62720 B

// ---------------- device scratch ----------------
__device__ __align__(16) float g_Wq[KVC*NH];
__device__ float g_qb[NH];
__device__ float g_logits[(size_t)(NB*NH)*HWSZ];      // [b*16+n][s], 8 MiB
__device__ float g_mx[NB*NH];
__device__ float g_inv[NB*NH];
__device__ __align__(16) float g_partial[(size_t)(MTOT/BM)*NVAL];
__device__ __align__(16) __half g_xh[(size_t)MTOT*KVC];     // x in fp16, 128 MiB
__device__ __align__(16) __half g_WvTh[(size_t)NVAL*KVC];   // Wv^T fp16 [n][k]

// ---------------- helpers ----------------
__device__ __forceinline__ float cvt_tf32(float x){
    float r; asm("cvt.rna.tf32.f32 %0, %1;" : "=f"(r) : "f"(x)); return r;
}
__device__ __forceinline__ uint32_t smem_u32(const void* p){
    uint32_t a;
    asm("{ .reg .u64 t; cvta.to.shared.u64 t, %1; cvt.u32.u64 %0, t; }" : "=r"(a) : "l"(p));
    return a;
}
__device__ __forceinline__ void cp16(uint32_t dst, const void* src){
    asm volatile("cp.async.cg.shared.global [%0], [%1], 16;" :: "r"(dst), "l"(src) : "memory");
}
__device__ __forceinline__ void ldm_x4(uint32_t a, uint32_t r[4]){
    asm volatile("ldmatrix.sync.aligned.m8n8.x4.shared.b16 {%0,%1,%2,%3}, [%4];"
                 : "=r"(r[0]), "=r"(r[1]), "=r"(r[2]), "=r"(r[3]) : "r"(a));
}
// fp16-accumulate mma (full-rate path): D(f16x2 x2) = A*B + C(f16)
__device__ __forceinline__ void mma_f16acc(uint32_t d[2], const uint32_t a[4],
                                           uint32_t b0, uint32_t b1,
                                           uint32_t c0, uint32_t c1){
    asm volatile(
        "mma.sync.aligned.m16n8k16.row.col.f16.f16.f16.f16 "
        "{%0,%1},{%2,%3,%4,%5},{%6,%7},{%8,%9};\n"
        : "=r"(d[0]), "=r"(d[1])
        : "r"(a[0]), "r"(a[1]), "r"(a[2]), "r"(a[3]),
          "r"(b0), "r"(b1), "r"(c0), "r"(c1));
}
// m16n8k8 tf32 for the small logits GEMM
__device__ __forceinline__ void mma_tf32(float c[4],
                                         uint32_t a0, uint32_t a1, uint32_t a2, uint32_t a3,
                                         uint32_t b0, uint32_t b1){
    asm volatile(
        "mma.sync.aligned.m16n8k8.row.col.f32.tf32.tf32.f32 "
        "{%0,%1,%2,%3},{%4,%5,%6,%7},{%8,%9},{%0,%1,%2,%3};\n"
        : "+f"(c[0]), "+f"(c[1]), "+f"(c[2]), "+f"(c[3])
        : "r"(a0), "r"(a1), "r"(a2), "r"(a3), "r"(b0), "r"(b1));
}
__device__ __forceinline__ float fast_tanh(float x){
    x = fminf(fmaxf(x, -15.f), 15.f);
    float e = __expf(2.0f * x);
    return __fdividef(e - 1.0f, e + 1.0f);
}

// ---------------- kernel 0: prep = transpose+convert Wv  AND  fold query ----------
__global__ void prep(const float* __restrict__ Wv,
                     const float* __restrict__ Wk, const float* __restrict__ bk,
                     const float* __restrict__ q){
    int tx = threadIdx.x, ty = threadIdx.y;           // 32 x 8
    if (blockIdx.x < 32){
        __shared__ float t[32][33];
        int n0 = blockIdx.x * 32, k0 = blockIdx.y * 32;
        #pragma unroll
        for (int i = 0; i < 4; i++)
            t[ty + 8*i][tx] = Wv[(size_t)(k0 + ty + 8*i)*NVAL + n0 + tx];
        __syncthreads();
        #pragma unroll
        for (int i = 0; i < 4; i++)
            g_WvTh[(size_t)(n0 + ty + 8*i)*KVC + k0 + tx] = __float2half_rn(t[tx][ty + 8*i]);
    } else {
        int n = blockIdx.y;
        __shared__ float qs[HD];
        int tid = ty*32 + tx;                          // 0..255
        if (tid < HD) qs[tid] = q[n*HD + tid];
        __syncthreads();
        for (int c = tid; c < KVC; c += 256){
            float s = 0.f;
            #pragma unroll 8
            for (int d = 0; d < HD; d++) s += Wk[(size_t)c*NVAL + n*HD + d] * qs[d];
            g_Wq[c*NH + n] = s;
        }
        if (tid == 0){
            float s = 0.f;
            for (int d = 0; d < HD; d++) s += bk[n*HD + d] * qs[d];
            g_qb[n] = s;
        }
    }
}

// ---------------- kernel 1: logits GEMM + x->fp16 conversion ----------------
__global__ __launch_bounds__(256) void logits_gemm(const float* __restrict__ x){
    __shared__ float As[128][68];
    __shared__ float Bs[64][24];
    int tid  = threadIdx.x;
    int wid  = tid >> 5, lane = tid & 31;
    int g    = lane >> 2, tq = lane & 3;
    int bm0  = blockIdx.x * 128;

    float acc[2][4] = {};

    for (int kt = 0; kt < KVC/64; kt++){
        int k0 = kt * 64;
        #pragma unroll
        for (int i = 0; i < 8; i++){
            int idx = tid + 256*i;
            int row = idx >> 4, c4 = (idx & 15) * 4;
            float4 v = *reinterpret_cast<const float4*>(x + (size_t)(bm0+row)*KVC + k0 + c4);
            __half2 h0 = __floats2half2_rn(v.x, v.y);
            __half2 h1 = __floats2half2_rn(v.z, v.w);
            uint2 u;
            u.x = *reinterpret_cast<uint32_t*>(&h0);
            u.y = *reinterpret_cast<uint32_t*>(&h1);
            *reinterpret_cast<uint2*>(&g_xh[(size_t)(bm0+row)*KVC + k0 + c4]) = u;
            float* d = &As[row][c4];
            d[0]=cvt_tf32(v.x); d[1]=cvt_tf32(v.y); d[2]=cvt_tf32(v.z); d[3]=cvt_tf32(v.w);
        }
        {
            int k = tid >> 2, n4 = (tid & 3) * 4;
            float4 v = *reinterpret_cast<const float4*>(g_Wq + (k0+k)*NH + n4);
            float* d = &Bs[k][n4];
            d[0]=cvt_tf32(v.x); d[1]=cvt_tf32(v.y); d[2]=cvt_tf32(v.z); d[3]=cvt_tf32(v.w);
        }
        __syncthreads();
        #pragma unroll
        for (int ks = 0; ks < 8; ks++){
            int m = wid*16 + g;
            uint32_t a0 = __float_as_uint(As[m    ][ks*8 + tq    ]);
            uint32_t a1 = __float_as_uint(As[m + 8][ks*8 + tq    ]);
            uint32_t a2 = __float_as_uint(As[m    ][ks*8 + tq + 4]);
            uint32_t a3 = __float_as_uint(As[m + 8][ks*8 + tq + 4]);
            #pragma unroll
            for (int ni = 0; ni < 2; ni++){
                uint32_t b0 = __float_as_uint(Bs[ks*8 + tq    ][ni*8 + g]);
                uint32_t b1 = __float_as_uint(Bs[ks*8 + tq + 4][ni*8 + g]);
                mma_tf32(acc[ni], a0,a1,a2,a3, b0,b1);
            }
        }
        __syncthreads();
    }
    #pragma unroll
    for (int ni = 0; ni < 2; ni++){
        #pragma unroll
        for (int r = 0; r < 4; r++){
            int row  = bm0 + wid*16 + g + ((r >= 2) ? 8 : 0);
            int head = ni*8 + 2*tq + (r & 1);
            int b = row >> 12, s = row & 4095;
            g_logits[(size_t)(b*NH + head)*HWSZ + s] = acc[ni][r] + g_qb[head];
        }
    }
}

// ---------------- kernel 2: softmax stats ----------------
__global__ void softmax_stats(){
    __shared__ float sm[256];
    int row = blockIdx.x, tid = threadIdx.x;
    const float* lp = g_logits + (size_t)row * HWSZ;
    float m = -1e30f;
    for (int i = tid; i < HWSZ; i += 256) m = fmaxf(m, lp[i]);
    sm[tid] = m; __syncthreads();
    for (int o = 128; o > 0; o >>= 1){
        if (tid < o) sm[tid] = fmaxf(sm[tid], sm[tid+o]);
        __syncthreads();
    }
    float mrow = sm[0];
    __syncthreads();
    float s = 0.f;
    for (int i = tid; i < HWSZ; i += 256) s += __expf(lp[i] - mrow);
    sm[tid] = s; __syncthreads();
    for (int o = 128; o > 0; o >>= 1){
        if (tid < o) sm[tid] += sm[tid+o];
        __syncthreads();
    }
    if (tid == 0){ g_mx[row] = mrow; g_inv[row] = 1.0f / sm[0]; }
}

// ---------------- kernel 3: fp16 value GEMM (fp16-acc mma, per-chunk f32 promote) ----
// BM=128 x BN=64, 256 threads (8 warps, 4x2), warp tile 32x32, 4-stage cp.async
__global__ void __launch_bounds__(256, 2) value_f16(const float* __restrict__ bv){
    extern __shared__ char smc[];
    float* smf = (float*)smc;
    uint32_t sb = smem_u32(smc);
    int tid = threadIdx.x;
    int wid = tid >> 5, lane = tid & 31;
    int wm  = wid >> 1, wn = wid & 1;       // 4 x 2 warp grid, warp tile 32x32
    int bn0 = blockIdx.x * BN;
    int mt  = blockIdx.y;
    int bm0 = mt * BM;
    int g   = lane >> 2, tq = lane & 3;

    if (tid < BN) smf[(OFF_BV>>2) + tid] = bv[bn0 + tid];

    // cp.async mapping
    int rowA = tid >> 1, grA = (tid & 1) * 2;
    int rowB = tid >> 2, grB = tid & 3;
    const __half* srcA = g_xh   + (size_t)(bm0 + rowA)*KVC + grA*8;
    const __half* srcB = g_WvTh + (size_t)(bn0 + rowB)*KVC + grB*8;
    uint32_t dstA = sb + rowA*ROWB + grA*16;
    uint32_t dstB = sb + A_BYTES + rowB*ROWB + grB*16;

    // hoisted ldmatrix bases (stage 0)
    int lrow = lane & 15, lhi = lane >> 4;
    uint32_t Ab0 = sb + (wm*32 + lrow)*ROWB + lhi*16;
    uint32_t Bb0 = sb + A_BYTES + (wn*32 + lrow)*ROWB + lhi*16;

    #define LOAD_STAGE(kt) do{ \
        const uint32_t so = (uint32_t)((kt) % NSTAGE) * STAGE_B; \
        const int ko = (kt) * BK; \
        cp16(dstA + so,      srcA + ko); \
        cp16(dstA + so + 16, srcA + ko + 8); \
        cp16(dstB + so,      srcB + ko); \
    } while(0)

    LOAD_STAGE(0);
    asm volatile("cp.async.commit_group;" ::: "memory");
    LOAD_STAGE(1);
    asm volatile("cp.async.commit_group;" ::: "memory");
    LOAD_STAGE(2);
    asm volatile("cp.async.commit_group;" ::: "memory");

    float acc[2][4][4] = {};                 // persistent f32 accumulators (32 regs)

    #pragma unroll
    for (int kt = 0; kt < NCHUNK; kt++){
        asm volatile("cp.async.wait_group 2;" ::: "memory");
        __syncthreads();
        if (kt + 3 < NCHUNK){
            LOAD_STAGE(kt + 3);
        }
        asm volatile("cp.async.commit_group;" ::: "memory");

        const uint32_t so = (uint32_t)(kt % NSTAGE) * STAGE_B;  // constant after unroll
        const uint32_t Ab = Ab0 + so;
        const uint32_t Bb = Bb0 + so;

        uint32_t d[2][4][2];                 // fp16 chunk accumulators

        #pragma unroll
        for (int ks = 0; ks < 2; ks++){
            const uint32_t gsel = ks*32;
            uint32_t a[2][4];
            #pragma unroll
            for (int mi = 0; mi < 2; mi++)
                ldm_x4(Ab + mi*(16*ROWB) + gsel, a[mi]);
            uint32_t b[4][2];
            #pragma unroll
            for (int np = 0; np < 2; np++){
                uint32_t r[4];
                ldm_x4(Bb + np*(16*ROWB) + gsel, r);
                b[2*np  ][0] = r[0]; b[2*np  ][1] = r[2];
                b[2*np+1][0] = r[1]; b[2*np+1][1] = r[3];
            }
            #pragma unroll
            for (int mi = 0; mi < 2; mi++)
                #pragma unroll
                for (int ni = 0; ni < 4; ni++){
                    uint32_t c0 = (ks == 0) ? 0u : d[mi][ni][0];
                    uint32_t c1 = (ks == 0) ? 0u : d[mi][ni][1];
                    mma_f16acc(d[mi][ni], a[mi], b[ni][0], b[ni][1], c0, c1);
                }
        }
        // promote chunk partials (K=32 in fp16) into f32 accumulators
        #pragma unroll
        for (int mi = 0; mi < 2; mi++)
            #pragma unroll
            for (int ni = 0; ni < 4; ni++){
                float2 f0 = __half22float2(*reinterpret_cast<__half2*>(&d[mi][ni][0]));
                float2 f1 = __half22float2(*reinterpret_cast<__half2*>(&d[mi][ni][1]));
                acc[mi][ni][0] += f0.x;
                acc[mi][ni][1] += f0.y;
                acc[mi][ni][2] += f1.x;
                acc[mi][ni][3] += f1.y;
            }
    }

    // ---- epilogue: softmax weights + tanh + reduce over 128 tile rows ----
    int head = bn0 >> 6;                     // whole CTA tile lies in one head
    float wgt[4];
    #pragma unroll
    for (int mi = 0; mi < 2; mi++){
        #pragma unroll
        for (int rg = 0; rg < 2; rg++){
            int p  = bm0 + wm*32 + mi*16 + g + rg*8;
            int b  = p >> 12, s = p & 4095;
            int bh = b*NH + head;
            wgt[mi*2+rg] = __expf(g_logits[((size_t)bh << 12) + s] - g_mx[bh]) * g_inv[bh];
        }
    }

    float* bvs = smf + (OFF_BV >> 2);
    float colsum[8] = {};
    #pragma unroll
    for (int mi = 0; mi < 2; mi++){
        #pragma unroll
        for (int rg = 0; rg < 2; rg++){
            float w = wgt[mi*2+rg];
            #pragma unroll
            for (int ni = 0; ni < 4; ni++){
                #pragma unroll
                for (int c01 = 0; c01 < 2; c01++){
                    int j = wn*32 + ni*8 + 2*tq + c01;
                    float t = fast_tanh(acc[mi][ni][rg*2 + c01] + bvs[j]);
                    colsum[ni*2 + c01] += w * t;
                }
            }
        }
    }
    #pragma unroll
    for (int i = 0; i < 8; i++){
        colsum[i] += __shfl_xor_sync(0xffffffffu, colsum[i], 16);
        colsum[i] += __shfl_xor_sync(0xffffffffu, colsum[i], 8);
        colsum[i] += __shfl_xor_sync(0xffffffffu, colsum[i], 4);
    }
    float* red = smf + (OFF_RED >> 2);       // [8 warps][32 cols]
    if (lane < 4){
        #pragma unroll
        for (int ni = 0; ni < 4; ni++)
            #pragma unroll
            for (int c01 = 0; c01 < 2; c01++)
                red[wid*32 + ni*8 + 2*tq + c01] = colsum[ni*2 + c01];
    }
    __syncthreads();
    if (tid < BN){
        int wn2 = tid >> 5, c = tid & 31;    // output col = wn2*32 + c
        float v = 0.f;
        #pragma unroll
        for (int wmm = 0; wmm < 4; wmm++)
            v += red[(wmm*2 + wn2)*32 + c];
        g_partial[(size_t)mt*NVAL + bn0 + tid] = v;   // unique writer -> deterministic
    }
}

// ---------------- kernel 4: reduce partials ----------------
__global__ void reduce_out(float* __restrict__ out){
    int o = blockIdx.x * 256 + threadIdx.x;   // 32768 outputs [b][n][v]
    int b = o >> 10, j = o & 1023;
    float s = 0.f;
    #pragma unroll
    for (int i = 0; i < 32; i++)
        s += g_partial[(size_t)(b*32 + i)*NVAL + j];
    out[o] = s;
}

// ---------------- launch ----------------
extern "C" void kernel_launch(void* const* d_in, const int* in_sizes, int n_in,
                              void* d_out, int out_size){
    const float* kv = (const float*)d_in[0];
    const float* Wk = (const float*)d_in[1];
    const float* bk = (const float*)d_in[2];
    const float* Wv = (const float*)d_in[3];
    const float* bv = (const float*)d_in[4];
    const float* q  = (const float*)d_in[5];
    float* out = (float*)d_out;

    static bool attr_done = false;
    if (!attr_done){
        cudaFuncSetAttribute(value_f16, cudaFuncAttributeMaxDynamicSharedMemorySize, SMEMB);
        attr_done = true;
    }

    prep<<<dim3(33, 16), dim3(32, 8)>>>(Wv, Wk, bk, q);
    logits_gemm<<<MTOT/128, 256>>>(kv);
    softmax_stats<<<NB*NH, 256>>>();
    value_f16<<<dim3(NVAL/BN, MTOT/BM), 256, SMEMB>>>(bv);
    reduce_out<<<(NB*NVAL)/256, 256>>>(out);
}

// round 13
// speedup vs baseline: 1.0920x; 1.0920x over previous
#include <cuda_runtime.h>
#include <cuda_fp16.h>
#include <cstdint>

// Problem constants
#define KVC   512
#define NH    16
#define HD    64
#define HWSZ  4096
#define NB    32
#define MTOT  (NB*HWSZ)     // 131072 pixels
#define NVAL  1024          // NH*HD value columns

// value-kernel tiles: BM=128 x BN=64, 256 threads (8 warps, 4x2), warp tile 32x32
#define BM      128
#define BN      64
#define BK      32
#define NCHUNK  (KVC/BK)    // 16
#define NSTAGE  4
#define ROWB    80          // 32 fp16 = 64B + 16B pad (conflict-free ldmatrix)
#define A_BYTES (BM*ROWB)              // 10240
#define STAGE_B ((BM+BN)*ROWB)         // 15360
#define OFF_RED (NSTAGE*STAGE_B)       // red[8][32] floats = 1024 B
#define OFF_BV  (OFF_RED + 1024)       // bv tile [64] = 256 B
#define SMEMB   (OFF_BV + BN*4)        // 62720 B

// ---------------- device scratch ----------------
__device__ __align__(16) float g_Wq[KVC*NH];
__device__ float g_qb[NH];
__device__ float g_logits[(size_t)(NB*NH)*HWSZ];      // [b*16+n][s], 8 MiB
__device__ float g_mx[NB*NH];
__device__ float g_inv[NB*NH];
__device__ __align__(16) float g_partial[(size_t)(MTOT/BM)*NVAL];
__device__ __align__(16) __half g_xh[(size_t)MTOT*KVC];     // x in fp16, 128 MiB
__device__ __align__(16) __half g_WvTh[(size_t)NVAL*KVC];   // Wv^T fp16 [n][k]

// ---------------- helpers ----------------
__device__ __forceinline__ float cvt_tf32(float x){
    float r; asm("cvt.rna.tf32.f32 %0, %1;" : "=f"(r) : "f"(x)); return r;
}
__device__ __forceinline__ uint32_t smem_u32(const void* p){
    uint32_t a;
    asm("{ .reg .u64 t; cvta.to.shared.u64 t, %1; cvt.u32.u64 %0, t; }" : "=r"(a) : "l"(p));
    return a;
}
__device__ __forceinline__ void cp16(uint32_t dst, const void* src){
    asm volatile("cp.async.cg.shared.global [%0], [%1], 16;" :: "r"(dst), "l"(src) : "memory");
}
__device__ __forceinline__ void ldm_x4(uint32_t a, uint32_t r[4]){
    asm volatile("ldmatrix.sync.aligned.m8n8.x4.shared.b16 {%0,%1,%2,%3}, [%4];"
                 : "=r"(r[0]), "=r"(r[1]), "=r"(r[2]), "=r"(r[3]) : "r"(a));
}
// fp16-accumulate mma (rt=8 full-rate path): D = A*B + D, all fp16
__device__ __forceinline__ void mma_f16acc(uint32_t d[2], const uint32_t a[4],
                                           uint32_t b0, uint32_t b1){
    asm volatile(
        "mma.sync.aligned.m16n8k16.row.col.f16.f16.f16.f16 "
        "{%0,%1},{%2,%3,%4,%5},{%6,%7},{%0,%1};\n"
        : "+r"(d[0]), "+r"(d[1])
        : "r"(a[0]), "r"(a[1]), "r"(a[2]), "r"(a[3]), "r"(b0), "r"(b1));
}
// m16n8k8 tf32 for the small logits GEMM
__device__ __forceinline__ void mma_tf32(float c[4],
                                         uint32_t a0, uint32_t a1, uint32_t a2, uint32_t a3,
                                         uint32_t b0, uint32_t b1){
    asm volatile(
        "mma.sync.aligned.m16n8k8.row.col.f32.tf32.tf32.f32 "
        "{%0,%1,%2,%3},{%4,%5,%6,%7},{%8,%9},{%0,%1,%2,%3};\n"
        : "+f"(c[0]), "+f"(c[1]), "+f"(c[2]), "+f"(c[3])
        : "r"(a0), "r"(a1), "r"(a2), "r"(a3), "r"(b0), "r"(b1));
}
__device__ __forceinline__ float fast_tanh(float x){
    x = fminf(fmaxf(x, -15.f), 15.f);
    float e = __expf(2.0f * x);
    return __fdividef(e - 1.0f, e + 1.0f);
}

// ---------------- kernel 0: prep = transpose+convert Wv  AND  fold query ----------
__global__ void prep(const float* __restrict__ Wv,
                     const float* __restrict__ Wk, const float* __restrict__ bk,
                     const float* __restrict__ q){
    int tx = threadIdx.x, ty = threadIdx.y;           // 32 x 8
    if (blockIdx.x < 32){
        __shared__ float t[32][33];
        int n0 = blockIdx.x * 32, k0 = blockIdx.y * 32;
        #pragma unroll
        for (int i = 0; i < 4; i++)
            t[ty + 8*i][tx] = Wv[(size_t)(k0 + ty + 8*i)*NVAL + n0 + tx];
        __syncthreads();
        #pragma unroll
        for (int i = 0; i < 4; i++)
            g_WvTh[(size_t)(n0 + ty + 8*i)*KVC + k0 + tx] = __float2half_rn(t[tx][ty + 8*i]);
    } else {
        int n = blockIdx.y;
        __shared__ float qs[HD];
        int tid = ty*32 + tx;                          // 0..255
        if (tid < HD) qs[tid] = q[n*HD + tid];
        __syncthreads();
        for (int c = tid; c < KVC; c += 256){
            float s = 0.f;
            #pragma unroll 8
            for (int d = 0; d < HD; d++) s += Wk[(size_t)c*NVAL + n*HD + d] * qs[d];
            g_Wq[c*NH + n] = s;
        }
        if (tid == 0){
            float s = 0.f;
            for (int d = 0; d < HD; d++) s += bk[n*HD + d] * qs[d];
            g_qb[n] = s;
        }
    }
}

// ---------------- kernel 1: logits GEMM + x->fp16 conversion ----------------
__global__ __launch_bounds__(256) void logits_gemm(const float* __restrict__ x){
    __shared__ float As[128][68];
    __shared__ float Bs[64][24];
    int tid  = threadIdx.x;
    int wid  = tid >> 5, lane = tid & 31;
    int g    = lane >> 2, tq = lane & 3;
    int bm0  = blockIdx.x * 128;

    float acc[2][4] = {};

    for (int kt = 0; kt < KVC/64; kt++){
        int k0 = kt * 64;
        #pragma unroll
        for (int i = 0; i < 8; i++){
            int idx = tid + 256*i;
            int row = idx >> 4, c4 = (idx & 15) * 4;
            float4 v = *reinterpret_cast<const float4*>(x + (size_t)(bm0+row)*KVC + k0 + c4);
            __half2 h0 = __floats2half2_rn(v.x, v.y);
            __half2 h1 = __floats2half2_rn(v.z, v.w);
            uint2 u;
            u.x = *reinterpret_cast<uint32_t*>(&h0);
            u.y = *reinterpret_cast<uint32_t*>(&h1);
            *reinterpret_cast<uint2*>(&g_xh[(size_t)(bm0+row)*KVC + k0 + c4]) = u;
            float* d = &As[row][c4];
            d[0]=cvt_tf32(v.x); d[1]=cvt_tf32(v.y); d[2]=cvt_tf32(v.z); d[3]=cvt_tf32(v.w);
        }
        {
            int k = tid >> 2, n4 = (tid & 3) * 4;
            float4 v = *reinterpret_cast<const float4*>(g_Wq + (k0+k)*NH + n4);
            float* d = &Bs[k][n4];
            d[0]=cvt_tf32(v.x); d[1]=cvt_tf32(v.y); d[2]=cvt_tf32(v.z); d[3]=cvt_tf32(v.w);
        }
        __syncthreads();
        #pragma unroll
        for (int ks = 0; ks < 8; ks++){
            int m = wid*16 + g;
            uint32_t a0 = __float_as_uint(As[m    ][ks*8 + tq    ]);
            uint32_t a1 = __float_as_uint(As[m + 8][ks*8 + tq    ]);
            uint32_t a2 = __float_as_uint(As[m    ][ks*8 + tq + 4]);
            uint32_t a3 = __float_as_uint(As[m + 8][ks*8 + tq + 4]);
            #pragma unroll
            for (int ni = 0; ni < 2; ni++){
                uint32_t b0 = __float_as_uint(Bs[ks*8 + tq    ][ni*8 + g]);
                uint32_t b1 = __float_as_uint(Bs[ks*8 + tq + 4][ni*8 + g]);
                mma_tf32(acc[ni], a0,a1,a2,a3, b0,b1);
            }
        }
        __syncthreads();
    }
    #pragma unroll
    for (int ni = 0; ni < 2; ni++){
        #pragma unroll
        for (int r = 0; r < 4; r++){
            int row  = bm0 + wid*16 + g + ((r >= 2) ? 8 : 0);
            int head = ni*8 + 2*tq + (r & 1);
            int b = row >> 12, s = row & 4095;
            g_logits[(size_t)(b*NH + head)*HWSZ + s] = acc[ni][r] + g_qb[head];
        }
    }
}

// ---------------- kernel 2: softmax stats ----------------
__global__ void softmax_stats(){
    __shared__ float sm[256];
    int row = blockIdx.x, tid = threadIdx.x;
    const float* lp = g_logits + (size_t)row * HWSZ;
    float m = -1e30f;
    for (int i = tid; i < HWSZ; i += 256) m = fmaxf(m, lp[i]);
    sm[tid] = m; __syncthreads();
    for (int o = 128; o > 0; o >>= 1){
        if (tid < o) sm[tid] = fmaxf(sm[tid], sm[tid+o]);
        __syncthreads();
    }
    float mrow = sm[0];
    __syncthreads();
    float s = 0.f;
    for (int i = tid; i < HWSZ; i += 256) s += __expf(lp[i] - mrow);
    sm[tid] = s; __syncthreads();
    for (int o = 128; o > 0; o >>= 1){
        if (tid < o) sm[tid] += sm[tid+o];
        __syncthreads();
    }
    if (tid == 0){ g_mx[row] = mrow; g_inv[row] = 1.0f / sm[0]; }
}

// ---------------- kernel 3: value GEMM, fp16-acc mma (rt=8), promote every K=64 ----
// BM=128 x BN=64, 256 threads (8 warps, 4x2), warp tile 32x32, 4-stage cp.async
__global__ void __launch_bounds__(256, 2) value_f16(const float* __restrict__ bv){
    extern __shared__ char smc[];
    float* smf = (float*)smc;
    uint32_t sb = smem_u32(smc);
    int tid = threadIdx.x;
    int wid = tid >> 5, lane = tid & 31;
    int wm  = wid >> 1, wn = wid & 1;       // 4 x 2 warp grid, warp tile 32x32
    int bn0 = blockIdx.x * BN;
    int mt  = blockIdx.y;
    int bm0 = mt * BM;
    int g   = lane >> 2, tq = lane & 3;

    if (tid < BN) smf[(OFF_BV>>2) + tid] = bv[bn0 + tid];

    // cp.async mapping
    int rowA = tid >> 1, grA = (tid & 1) * 2;
    int rowB = tid >> 2, grB = tid & 3;
    const __half* srcA = g_xh   + (size_t)(bm0 + rowA)*KVC + grA*8;
    const __half* srcB = g_WvTh + (size_t)(bn0 + rowB)*KVC + grB*8;
    uint32_t dstA = sb + rowA*ROWB + grA*16;
    uint32_t dstB = sb + A_BYTES + rowB*ROWB + grB*16;

    // hoisted ldmatrix bases (stage 0)
    int lrow = lane & 15, lhi = lane >> 4;
    uint32_t Ab0 = sb + (wm*32 + lrow)*ROWB + lhi*16;
    uint32_t Bb0 = sb + A_BYTES + (wn*32 + lrow)*ROWB + lhi*16;

    #define LOAD_STAGE(kt) do{ \
        const uint32_t so = (uint32_t)((kt) % NSTAGE) * STAGE_B; \
        const int ko = (kt) * BK; \
        cp16(dstA + so,      srcA + ko); \
        cp16(dstA + so + 16, srcA + ko + 8); \
        cp16(dstB + so,      srcB + ko); \
    } while(0)

    LOAD_STAGE(0);
    asm volatile("cp.async.commit_group;" ::: "memory");
    LOAD_STAGE(1);
    asm volatile("cp.async.commit_group;" ::: "memory");
    LOAD_STAGE(2);
    asm volatile("cp.async.commit_group;" ::: "memory");

    float    acc[2][4][4] = {};              // persistent f32 accumulators (32 regs)
    uint32_t d[2][4][2];                     // fp16 pair-of-chunks accumulators (16 regs)

    #pragma unroll
    for (int kp = 0; kp < NCHUNK/2; kp++){   // 8 chunk-pairs (K=64 each in fp16)
        // zero d for this pair
        #pragma unroll
        for (int mi = 0; mi < 2; mi++)
            #pragma unroll
            for (int ni = 0; ni < 4; ni++){
                d[mi][ni][0] = 0u; d[mi][ni][1] = 0u;
            }

        #pragma unroll
        for (int half = 0; half < 2; half++){
            const int kt = 2*kp + half;
            asm volatile("cp.async.wait_group 2;" ::: "memory");
            __syncthreads();
            if (kt + 3 < NCHUNK){
                LOAD_STAGE(kt + 3);
            }
            asm volatile("cp.async.commit_group;" ::: "memory");

            const uint32_t so = (uint32_t)(kt % NSTAGE) * STAGE_B;  // constant after unroll
            const uint32_t Ab = Ab0 + so;
            const uint32_t Bb = Bb0 + so;

            #pragma unroll
            for (int ks = 0; ks < 2; ks++){
                const uint32_t gsel = ks*32;
                uint32_t a[2][4];
                #pragma unroll
                for (int mi = 0; mi < 2; mi++)
                    ldm_x4(Ab + mi*(16*ROWB) + gsel, a[mi]);
                uint32_t b[4][2];
                #pragma unroll
                for (int np = 0; np < 2; np++){
                    uint32_t r[4];
                    ldm_x4(Bb + np*(16*ROWB) + gsel, r);
                    b[2*np  ][0] = r[0]; b[2*np  ][1] = r[2];
                    b[2*np+1][0] = r[1]; b[2*np+1][1] = r[3];
                }
                #pragma unroll
                for (int mi = 0; mi < 2; mi++)
                    #pragma unroll
                    for (int ni = 0; ni < 4; ni++)
                        mma_f16acc(d[mi][ni], a[mi], b[ni][0], b[ni][1]);
            }
        }
        // promote K=64 fp16 partials into persistent f32 accumulators
        #pragma unroll
        for (int mi = 0; mi < 2; mi++)
            #pragma unroll
            for (int ni = 0; ni < 4; ni++){
                float2 f0 = __half22float2(*reinterpret_cast<__half2*>(&d[mi][ni][0]));
                float2 f1 = __half22float2(*reinterpret_cast<__half2*>(&d[mi][ni][1]));
                acc[mi][ni][0] += f0.x;
                acc[mi][ni][1] += f0.y;
                acc[mi][ni][2] += f1.x;
                acc[mi][ni][3] += f1.y;
            }
    }

    // ---- epilogue: softmax weights + tanh + reduce over 128 tile rows ----
    int head = bn0 >> 6;                     // whole CTA tile lies in one head
    float wgt[4];
    #pragma unroll
    for (int mi = 0; mi < 2; mi++){
        #pragma unroll
        for (int rg = 0; rg < 2; rg++){
            int p  = bm0 + wm*32 + mi*16 + g + rg*8;
            int b  = p >> 12, s = p & 4095;
            int bh = b*NH + head;
            wgt[mi*2+rg] = __expf(g_logits[((size_t)bh << 12) + s] - g_mx[bh]) * g_inv[bh];
        }
    }

    float* bvs = smf + (OFF_BV >> 2);
    float colsum[8] = {};
    #pragma unroll
    for (int mi = 0; mi < 2; mi++){
        #pragma unroll
        for (int rg = 0; rg < 2; rg++){
            float w = wgt[mi*2+rg];
            #pragma unroll
            for (int ni = 0; ni < 4; ni++){
                #pragma unroll
                for (int c01 = 0; c01 < 2; c01++){
                    int j = wn*32 + ni*8 + 2*tq + c01;
                    float t = fast_tanh(acc[mi][ni][rg*2 + c01] + bvs[j]);
                    colsum[ni*2 + c01] += w * t;
                }
            }
        }
    }
    #pragma unroll
    for (int i = 0; i < 8; i++){
        colsum[i] += __shfl_xor_sync(0xffffffffu, colsum[i], 16);
        colsum[i] += __shfl_xor_sync(0xffffffffu, colsum[i], 8);
        colsum[i] += __shfl_xor_sync(0xffffffffu, colsum[i], 4);
    }
    float* red = smf + (OFF_RED >> 2);       // [8 warps][32 cols]
    if (lane < 4){
        #pragma unroll
        for (int ni = 0; ni < 4; ni++)
            #pragma unroll
            for (int c01 = 0; c01 < 2; c01++)
                red[wid*32 + ni*8 + 2*tq + c01] = colsum[ni*2 + c01];
    }
    __syncthreads();
    if (tid < BN){
        int wn2 = tid >> 5, c = tid & 31;    // output col = wn2*32 + c
        float v = 0.f;
        #pragma unroll
        for (int wmm = 0; wmm < 4; wmm++)
            v += red[(wmm*2 + wn2)*32 + c];
        g_partial[(size_t)mt*NVAL + bn0 + tid] = v;   // unique writer -> deterministic
    }
}

// ---------------- kernel 4: reduce partials ----------------
__global__ void reduce_out(float* __restrict__ out){
    int o = blockIdx.x * 256 + threadIdx.x;   // 32768 outputs [b][n][v]
    int b = o >> 10, j = o & 1023;
    float s = 0.f;
    #pragma unroll
    for (int i = 0; i < 32; i++)
        s += g_partial[(size_t)(b*32 + i)*NVAL + j];
    out[o] = s;
}

// ---------------- launch ----------------
extern "C" void kernel_launch(void* const* d_in, const int* in_sizes, int n_in,
                              void* d_out, int out_size){
    const float* kv = (const float*)d_in[0];
    const float* Wk = (const float*)d_in[1];
    const float* bk = (const float*)d_in[2];
    const float* Wv = (const float*)d_in[3];
    const float* bv = (const float*)d_in[4];
    const float* q  = (const float*)d_in[5];
    float* out = (float*)d_out;

    static bool attr_done = false;
    if (!attr_done){
        cudaFuncSetAttribute(value_f16, cudaFuncAttributeMaxDynamicSharedMemorySize, SMEMB);
        attr_done = true;
    }

    prep<<<dim3(33, 16), dim3(32, 8)>>>(Wv, Wk, bk, q);
    logits_gemm<<<MTOT/128, 256>>>(kv);
    softmax_stats<<<NB*NH, 256>>>();
    value_f16<<<dim3(NVAL/BN, MTOT/BM), 256, SMEMB>>>(bv);
    reduce_out<<<(NB*NVAL)/256, 256>>>(out);
}

// round 16
// speedup vs baseline: 1.2330x; 1.1292x over previous
#include <cuda_runtime.h>
#include <cuda_fp16.h>
#include <cstdint>

// Problem constants
#define KVC   512
#define NH    16
#define HD    64
#define HWSZ  4096
#define NB    32
#define MTOT  (NB*HWSZ)     // 131072 pixels
#define NVAL  1024          // NH*HD value columns

// value-kernel tiles: BM=128 x BN=256, 512 threads, warp tile 64x32 (R8 geometry)
#define BM      128
#define BN      256
#define BK      32
#define NCHUNK  (KVC/BK)    // 16
#define NSTAGE  4
#define ROWB    80          // 32 fp16 = 64B + 16B pad (conflict-free ldmatrix)
#define A_BYTES (BM*ROWB)              // 10240
#define STAGE_B ((BM+BN)*ROWB)         // 30720
#define OFF_RED (NSTAGE*STAGE_B)       // red[16][32] floats = 2048 B
#define OFF_BV  (OFF_RED + 2048)       // bv tile [256] = 1024 B
#define SMEMB   (OFF_BV + BN*4)        // 125952 B -> 1 CTA/SM (16 warps)

// ---------------- device scratch ----------------
__device__ __align__(16) float g_Wq[KVC*NH];
__device__ float g_qb[NH];
__device__ float g_logits[(size_t)(NB*NH)*HWSZ];      // [b*16+n][s], 8 MiB
__device__ float g_mx[NB*NH];
__device__ float g_inv[NB*NH];
__device__ __align__(16) float g_partial[(size_t)(MTOT/BM)*NVAL];
__device__ __align__(16) __half g_xh[(size_t)MTOT*KVC];     // x in fp16, 128 MiB
__device__ __align__(16) __half g_WvTh[(size_t)NVAL*KVC];   // Wv^T fp16 [n][k]

// ---------------- helpers ----------------
__device__ __forceinline__ float cvt_tf32(float x){
    float r; asm("cvt.rna.tf32.f32 %0, %1;" : "=f"(r) : "f"(x)); return r;
}
__device__ __forceinline__ uint32_t smem_u32(const void* p){
    uint32_t a;
    asm("{ .reg .u64 t; cvta.to.shared.u64 t, %1; cvt.u32.u64 %0, t; }" : "=r"(a) : "l"(p));
    return a;
}
__device__ __forceinline__ void cp16(uint32_t dst, const void* src){
    asm volatile("cp.async.cg.shared.global [%0], [%1], 16;" :: "r"(dst), "l"(src) : "memory");
}
__device__ __forceinline__ void ldm_x4(uint32_t a, uint32_t r[4]){
    asm volatile("ldmatrix.sync.aligned.m8n8.x4.shared.b16 {%0,%1,%2,%3}, [%4];"
                 : "=r"(r[0]), "=r"(r[1]), "=r"(r[2]), "=r"(r[3]) : "r"(a));
}
// fp16-accumulate mma (rt=8 full-rate path): D = A*B + D, all fp16
__device__ __forceinline__ void mma_f16acc(uint32_t d[2], const uint32_t a[4],
                                           uint32_t b0, uint32_t b1){
    asm volatile(
        "mma.sync.aligned.m16n8k16.row.col.f16.f16.f16.f16 "
        "{%0,%1},{%2,%3,%4,%5},{%6,%7},{%0,%1};\n"
        : "+r"(d[0]), "+r"(d[1])
        : "r"(a[0]), "r"(a[1]), "r"(a[2]), "r"(a[3]), "r"(b0), "r"(b1));
}
// m16n8k8 tf32 for the small logits GEMM
__device__ __forceinline__ void mma_tf32(float c[4],
                                         uint32_t a0, uint32_t a1, uint32_t a2, uint32_t a3,
                                         uint32_t b0, uint32_t b1){
    asm volatile(
        "mma.sync.aligned.m16n8k8.row.col.f32.tf32.tf32.f32 "
        "{%0,%1,%2,%3},{%4,%5,%6,%7},{%8,%9},{%0,%1,%2,%3};\n"
        : "+f"(c[0]), "+f"(c[1]), "+f"(c[2]), "+f"(c[3])
        : "r"(a0), "r"(a1), "r"(a2), "r"(a3), "r"(b0), "r"(b1));
}
__device__ __forceinline__ float fast_tanh(float x){
    x = fminf(fmaxf(x, -15.f), 15.f);
    float e = __expf(2.0f * x);
    return __fdividef(e - 1.0f, e + 1.0f);
}

// ---------------- kernel 0: prep = transpose+convert Wv  AND  fold query ----------
__global__ void prep(const float* __restrict__ Wv,
                     const float* __restrict__ Wk, const float* __restrict__ bk,
                     const float* __restrict__ q){
    int tx = threadIdx.x, ty = threadIdx.y;           // 32 x 8
    if (blockIdx.x < 32){
        __shared__ float t[32][33];
        int n0 = blockIdx.x * 32, k0 = blockIdx.y * 32;
        #pragma unroll
        for (int i = 0; i < 4; i++)
            t[ty + 8*i][tx] = Wv[(size_t)(k0 + ty + 8*i)*NVAL + n0 + tx];
        __syncthreads();
        #pragma unroll
        for (int i = 0; i < 4; i++)
            g_WvTh[(size_t)(n0 + ty + 8*i)*KVC + k0 + tx] = __float2half_rn(t[tx][ty + 8*i]);
    } else {
        int n = blockIdx.y;
        __shared__ float qs[HD];
        int tid = ty*32 + tx;                          // 0..255
        if (tid < HD) qs[tid] = q[n*HD + tid];
        __syncthreads();
        for (int c = tid; c < KVC; c += 256){
            float s = 0.f;
            #pragma unroll 8
            for (int d = 0; d < HD; d++) s += Wk[(size_t)c*NVAL + n*HD + d] * qs[d];
            g_Wq[c*NH + n] = s;
        }
        if (tid == 0){
            float s = 0.f;
            for (int d = 0; d < HD; d++) s += bk[n*HD + d] * qs[d];
            g_qb[n] = s;
        }
    }
}

// ---------------- kernel 1: logits GEMM + x->fp16 conversion ----------------
__global__ __launch_bounds__(256) void logits_gemm(const float* __restrict__ x){
    __shared__ float As[128][68];
    __shared__ float Bs[64][24];
    int tid  = threadIdx.x;
    int wid  = tid >> 5, lane = tid & 31;
    int g    = lane >> 2, tq = lane & 3;
    int bm0  = blockIdx.x * 128;

    float acc[2][4] = {};

    for (int kt = 0; kt < KVC/64; kt++){
        int k0 = kt * 64;
        #pragma unroll
        for (int i = 0; i < 8; i++){
            int idx = tid + 256*i;
            int row = idx >> 4, c4 = (idx & 15) * 4;
            float4 v = *reinterpret_cast<const float4*>(x + (size_t)(bm0+row)*KVC + k0 + c4);
            __half2 h0 = __floats2half2_rn(v.x, v.y);
            __half2 h1 = __floats2half2_rn(v.z, v.w);
            uint2 u;
            u.x = *reinterpret_cast<uint32_t*>(&h0);
            u.y = *reinterpret_cast<uint32_t*>(&h1);
            *reinterpret_cast<uint2*>(&g_xh[(size_t)(bm0+row)*KVC + k0 + c4]) = u;
            float* d = &As[row][c4];
            d[0]=cvt_tf32(v.x); d[1]=cvt_tf32(v.y); d[2]=cvt_tf32(v.z); d[3]=cvt_tf32(v.w);
        }
        {
            int k = tid >> 2, n4 = (tid & 3) * 4;
            float4 v = *reinterpret_cast<const float4*>(g_Wq + (k0+k)*NH + n4);
            float* d = &Bs[k][n4];
            d[0]=cvt_tf32(v.x); d[1]=cvt_tf32(v.y); d[2]=cvt_tf32(v.z); d[3]=cvt_tf32(v.w);
        }
        __syncthreads();
        #pragma unroll
        for (int ks = 0; ks < 8; ks++){
            int m = wid*16 + g;
            uint32_t a0 = __float_as_uint(As[m    ][ks*8 + tq    ]);
            uint32_t a1 = __float_as_uint(As[m + 8][ks*8 + tq    ]);
            uint32_t a2 = __float_as_uint(As[m    ][ks*8 + tq + 4]);
            uint32_t a3 = __float_as_uint(As[m + 8][ks*8 + tq + 4]);
            #pragma unroll
            for (int ni = 0; ni < 2; ni++){
                uint32_t b0 = __float_as_uint(Bs[ks*8 + tq    ][ni*8 + g]);
                uint32_t b1 = __float_as_uint(Bs[ks*8 + tq + 4][ni*8 + g]);
                mma_tf32(acc[ni], a0,a1,a2,a3, b0,b1);
            }
        }
        __syncthreads();
    }
    #pragma unroll
    for (int ni = 0; ni < 2; ni++){
        #pragma unroll
        for (int r = 0; r < 4; r++){
            int row  = bm0 + wid*16 + g + ((r >= 2) ? 8 : 0);
            int head = ni*8 + 2*tq + (r & 1);
            int b = row >> 12, s = row & 4095;
            g_logits[(size_t)(b*NH + head)*HWSZ + s] = acc[ni][r] + g_qb[head];
        }
    }
}

// ---------------- kernel 2: softmax stats ----------------
__global__ void softmax_stats(){
    __shared__ float sm[256];
    int row = blockIdx.x, tid = threadIdx.x;
    const float* lp = g_logits + (size_t)row * HWSZ;
    float m = -1e30f;
    for (int i = tid; i < HWSZ; i += 256) m = fmaxf(m, lp[i]);
    sm[tid] = m; __syncthreads();
    for (int o = 128; o > 0; o >>= 1){
        if (tid < o) sm[tid] = fmaxf(sm[tid], sm[tid+o]);
        __syncthreads();
    }
    float mrow = sm[0];
    __syncthreads();
    float s = 0.f;
    for (int i = tid; i < HWSZ; i += 256) s += __expf(lp[i] - mrow);
    sm[tid] = s; __syncthreads();
    for (int o = 128; o > 0; o >>= 1){
        if (tid < o) sm[tid] += sm[tid+o];
        __syncthreads();
    }
    if (tid == 0){ g_mx[row] = mrow; g_inv[row] = 1.0f / sm[0]; }
}

// ---------------- kernel 3: value GEMM, persistent fp16 accumulators (rt=8) -------
// BM=128 x BN=256, 512 threads (16 warps, 2x8), warp tile 64x32, 4-stage cp.async
__global__ void __launch_bounds__(512, 1) value_f16(const float* __restrict__ bv){
    extern __shared__ char smc[];
    float* smf = (float*)smc;
    uint32_t sb = smem_u32(smc);
    int tid = threadIdx.x;
    int wid = tid >> 5, lane = tid & 31;
    int wm  = wid >> 3, wn = wid & 7;       // 2 x 8 warp grid, warp tile 64x32
    int bn0 = blockIdx.x * BN;
    int mt  = blockIdx.y;
    int bm0 = mt * BM;
    int g   = lane >> 2, tq = lane & 3;

    if (tid < BN) smf[(OFF_BV>>2) + tid] = bv[bn0 + tid];

    // cp.async mapping: A: 1 granule/thread; B: 2 granules/thread
    int rowA = tid >> 2, grA = tid & 3;
    int rowB = tid >> 1, grB = (tid & 1) * 2;
    const __half* srcA = g_xh   + (size_t)(bm0 + rowA)*KVC + grA*8;
    const __half* srcB = g_WvTh + (size_t)(bn0 + rowB)*KVC + grB*8;
    uint32_t dstA = sb + rowA*ROWB + grA*16;
    uint32_t dstB = sb + A_BYTES + rowB*ROWB + grB*16;

    // hoisted ldmatrix bases (stage 0)
    int lrow = lane & 15, lhi = lane >> 4;
    uint32_t Ab0 = sb + (wm*64 + lrow)*ROWB + lhi*16;
    uint32_t Bb0 = sb + A_BYTES + (wn*32 + lrow)*ROWB + lhi*16;

    #define LOAD_STAGE(kt) do{ \
        const uint32_t so = (uint32_t)((kt) % NSTAGE) * STAGE_B; \
        const int ko = (kt) * BK; \
        cp16(dstA + so,      srcA + ko); \
        cp16(dstB + so,      srcB + ko); \
        cp16(dstB + so + 16, srcB + ko + 8); \
    } while(0)

    LOAD_STAGE(0);
    asm volatile("cp.async.commit_group;" ::: "memory");
    LOAD_STAGE(1);
    asm volatile("cp.async.commit_group;" ::: "memory");
    LOAD_STAGE(2);
    asm volatile("cp.async.commit_group;" ::: "memory");

    // precompute softmax weights for this thread's 8 accumulator rows
    int head = (bn0 + wn*32) >> 6;           // warp's 32 cols lie within one head
    float wgt[8];
    #pragma unroll
    for (int mi = 0; mi < 4; mi++){
        #pragma unroll
        for (int rg = 0; rg < 2; rg++){
            int p  = bm0 + wm*64 + mi*16 + g + rg*8;
            int b  = p >> 12, s = p & 4095;
            int bh = b*NH + head;
            wgt[mi*2+rg] = __expf(g_logits[((size_t)bh << 12) + s] - g_mx[bh]) * g_inv[bh];
        }
    }

    uint32_t dacc[4][4][2] = {};             // persistent fp16x2 accumulators (32 regs)

    #pragma unroll
    for (int kt = 0; kt < NCHUNK; kt++){
        asm volatile("cp.async.wait_group 2;" ::: "memory");
        __syncthreads();
        if (kt + 3 < NCHUNK){                // constant predicate after unroll
            LOAD_STAGE(kt + 3);
        }
        asm volatile("cp.async.commit_group;" ::: "memory");

        const uint32_t so = (uint32_t)(kt % NSTAGE) * STAGE_B;  // constant
        const uint32_t Ab = Ab0 + so;
        const uint32_t Bb = Bb0 + so;

        #pragma unroll
        for (int ks = 0; ks < 2; ks++){
            const uint32_t gsel = ks*32;
            uint32_t a[4][4];
            #pragma unroll
            for (int mi = 0; mi < 4; mi++)
                ldm_x4(Ab + mi*(16*ROWB) + gsel, a[mi]);
            uint32_t b[4][2];
            #pragma unroll
            for (int np = 0; np < 2; np++){
                uint32_t r[4];
                ldm_x4(Bb + np*(16*ROWB) + gsel, r);
                b[2*np  ][0] = r[0]; b[2*np  ][1] = r[2];
                b[2*np+1][0] = r[1]; b[2*np+1][1] = r[3];
            }
            #pragma unroll
            for (int mi = 0; mi < 4; mi++)
                #pragma unroll
                for (int ni = 0; ni < 4; ni++)
                    mma_f16acc(dacc[mi][ni], a[mi], b[ni][0], b[ni][1]);
        }
    }

    // ---- epilogue: promote fp16 acc -> f32, tanh + weight + row reduce ----
    float* bvs = smf + (OFF_BV >> 2);
    float colsum[8] = {};
    #pragma unroll
    for (int mi = 0; mi < 4; mi++){
        float2 f0[4], f1[4];
        #pragma unroll
        for (int ni = 0; ni < 4; ni++){
            f0[ni] = __half22float2(*reinterpret_cast<__half2*>(&dacc[mi][ni][0]));
            f1[ni] = __half22float2(*reinterpret_cast<__half2*>(&dacc[mi][ni][1]));
        }
        #pragma unroll
        for (int rg = 0; rg < 2; rg++){
            float w = wgt[mi*2+rg];
            #pragma unroll
            for (int ni = 0; ni < 4; ni++){
                #pragma unroll
                for (int c01 = 0; c01 < 2; c01++){
                    int j = wn*32 + ni*8 + 2*tq + c01;
                    float aval = (rg == 0) ? ((c01 == 0) ? f0[ni].x : f0[ni].y)
                                           : ((c01 == 0) ? f1[ni].x : f1[ni].y);
                    float t = fast_tanh(aval + bvs[j]);
                    colsum[ni*2 + c01] += w * t;
                }
            }
        }
    }
    #pragma unroll
    for (int i = 0; i < 8; i++){
        colsum[i] += __shfl_xor_sync(0xffffffffu, colsum[i], 16);
        colsum[i] += __shfl_xor_sync(0xffffffffu, colsum[i], 8);
        colsum[i] += __shfl_xor_sync(0xffffffffu, colsum[i], 4);
    }
    float* red = smf + (OFF_RED >> 2);       // [16 warps][32 cols]
    if (lane < 4){
        #pragma unroll
        for (int ni = 0; ni < 4; ni++)
            #pragma unroll
            for (int c01 = 0; c01 < 2; c01++)
                red[(wm*8 + wn)*32 + ni*8 + 2*tq + c01] = colsum[ni*2 + c01];
    }
    __syncthreads();
    if (tid < BN){
        float v = red[(tid >> 5)*32 + (tid & 31)] + red[(8 + (tid >> 5))*32 + (tid & 31)];
        g_partial[(size_t)mt*NVAL + bn0 + tid] = v;   // unique writer -> deterministic
    }
}

// ---------------- kernel 4: reduce partials ----------------
__global__ void reduce_out(float* __restrict__ out){
    int o = blockIdx.x * 256 + threadIdx.x;   // 32768 outputs [b][n][v]
    int b = o >> 10, j = o & 1023;
    float s = 0.f;
    #pragma unroll
    for (int i = 0; i < 32; i++)
        s += g_partial[(size_t)(b*32 + i)*NVAL + j];
    out[o] = s;
}

// ---------------- launch ----------------
extern "C" void kernel_launch(void* const* d_in, const int* in_sizes, int n_in,
                              void* d_out, int out_size){
    const float* kv = (const float*)d_in[0];
    const float* Wk = (const float*)d_in[1];
    const float* bk = (const float*)d_in[2];
    const float* Wv = (const float*)d_in[3];
    const float* bv = (const float*)d_in[4];
    const float* q  = (const float*)d_in[5];
    float* out = (float*)d_out;

    static bool attr_done = false;
    if (!attr_done){
        cudaFuncSetAttribute(value_f16, cudaFuncAttributeMaxDynamicSharedMemorySize, SMEMB);
        attr_done = true;
    }

    prep<<<dim3(33, 16), dim3(32, 8)>>>(Wv, Wk, bk, q);
    logits_gemm<<<MTOT/128, 256>>>(kv);
    softmax_stats<<<NB*NH, 256>>>();
    value_f16<<<dim3(NVAL/BN, MTOT/BM), 512, SMEMB>>>(bv);
    reduce_out<<<(NB*NVAL)/256, 256>>>(out);
}